// round 1
// baseline (speedup 1.0000x reference)
#include <cuda_runtime.h>
#include <math.h>

typedef unsigned long long ull;

#define NP     1024
#define EMBD   64
#define HID    128
#define NCELL  64
#define KSOC   8192     // NCELL * HID
#define KSPLIT 8
#define NGATE  512
#define KX     256      // [emb(64) | pool(64) | h0(128)]
#define NOUT   120
#define MIX    20

// ---------------- device scratch (static, no allocations) ----------------
__device__ float g_social[NP * KSOC];            // 32 MB
__device__ float g_part[KSPLIT * NP * EMBD];     // 2 MB
__device__ float g_X[NP * KX];                   // 1 MB
__device__ float g_gates[NP * NGATE];            // 2 MB
__device__ float g_h[NP * HID];                  // 0.5 MB

// ---------------- f32x2 packed-FMA helpers (Blackwell FFMA2) ----------------
__device__ __forceinline__ ull pack2(float lo, float hi) {
    ull r; asm("mov.b64 %0, {%1, %2};" : "=l"(r) : "f"(lo), "f"(hi)); return r;
}
__device__ __forceinline__ void unpack2(ull v, float& lo, float& hi) {
    asm("mov.b64 {%0, %1}, %2;" : "=f"(lo), "=f"(hi) : "l"(v));
}
__device__ __forceinline__ ull fma2(ull a, ull b, ull c) {
    ull d; asm("fma.rn.f32x2 %0, %1, %2, %3;" : "=l"(d) : "l"(a), "l"(b), "l"(c)); return d;
}
__device__ __forceinline__ float sigm(float x) { return 1.0f / (1.0f + expf(-x)); }

// ---------------- K1: social pooling scatter (one CTA per pedestrian n) ----------------
__global__ __launch_bounds__(128) void social_kernel(const float* __restrict__ xabs,
                                                     const float* __restrict__ h0) {
    __shared__ float sx[NP];
    __shared__ float sy[NP];
    __shared__ float ssoc[NCELL * HID];   // 32 KB accumulator for this n
    __shared__ int   scell[128];

    const int n   = blockIdx.x;
    const int tid = threadIdx.x;

    for (int i = tid; i < NP; i += 128) {
        sx[i] = xabs[2 * i];
        sy[i] = xabs[2 * i + 1];
    }
    for (int c = tid; c < NCELL * HID; c += 128) ssoc[c] = 0.0f;
    __syncthreads();

    const float wl = sx[n] - 0.2f;   // width_low
    const float bl = sy[n] - 0.2f;   // height_low

    for (int m0 = 0; m0 < NP; m0 += 128) {
        const int m = m0 + tid;
        const float dx = sx[m] - wl;
        const float dy = sy[m] - bl;
        int cell = -1;
        if (dx >= 0.0f && dx < 0.4f && dy >= 0.0f && dy < 0.4f && m != n) {
            // match JAX exactly: (dx / 0.4) * 8, IEEE round-to-nearest divide
            const int cx = (int)floorf(__fdiv_rn(dx, 0.4f) * 8.0f);
            const int cy = (int)floorf(__fdiv_rn(dy, 0.4f) * 8.0f);
            if (cx >= 0 && cx < 8 && cy >= 0 && cy < 8) cell = cx + cy * 8;
        }
        scell[tid] = cell;
        __syncthreads();

        #pragma unroll 4
        for (int j = 0; j < 128; j++) {
            const int c = scell[j];
            if (c >= 0) {
                ssoc[c * HID + tid] += h0[(m0 + j) * HID + tid];
            }
        }
        __syncthreads();
    }

    #pragma unroll
    for (int c = 0; c < NCELL; c++)
        g_social[n * KSOC + c * HID + tid] = ssoc[c * HID + tid];
}

// ---------------- K2: social GEMM  part[split] = social_tile @ W_soc^T  ----------------
// M=1024 (16 row tiles of 64), N=64 (one tile), K=8192 split into 8 chunks of 1024.
__global__ __launch_bounds__(256) void gemm_social_kernel(const float* __restrict__ Wsoc) {
    __shared__ __align__(16) float As[64][33];
    __shared__ __align__(16) float Bs[32][66];

    const int row0  = blockIdx.x * 64;
    const int split = blockIdx.y;
    const int t  = threadIdx.x;
    const int tx = t & 15;
    const int ty = t >> 4;

    ull acc[4][2];
    #pragma unroll
    for (int r = 0; r < 4; r++) { acc[r][0] = pack2(0.f, 0.f); acc[r][1] = pack2(0.f, 0.f); }

    const int kbase = split * (KSOC / KSPLIT);
    for (int s = 0; s < (KSOC / KSPLIT) / 32; s++) {
        const int k0 = kbase + s * 32;
        #pragma unroll
        for (int i = 0; i < 8; i++) {
            const int idx = t + i * 256;
            const int mm = idx >> 5, kk = idx & 31;
            As[mm][kk] = g_social[(row0 + mm) * KSOC + k0 + kk];
        }
        #pragma unroll
        for (int i = 0; i < 8; i++) {
            const int idx = t + i * 256;
            const int ee = idx >> 5, kk = idx & 31;
            Bs[kk][ee] = Wsoc[ee * KSOC + k0 + kk];
        }
        __syncthreads();

        #pragma unroll
        for (int kk = 0; kk < 32; kk++) {
            const ull b01 = *(const ull*)&Bs[kk][tx * 4];
            const ull b23 = *(const ull*)&Bs[kk][tx * 4 + 2];
            #pragma unroll
            for (int r = 0; r < 4; r++) {
                const float a  = As[ty * 4 + r][kk];
                const ull   a2 = pack2(a, a);
                acc[r][0] = fma2(a2, b01, acc[r][0]);
                acc[r][1] = fma2(a2, b23, acc[r][1]);
            }
        }
        __syncthreads();
    }

    float* outp = g_part + split * (NP * EMBD);
    #pragma unroll
    for (int r = 0; r < 4; r++) {
        float4 v;
        unpack2(acc[r][0], v.x, v.y);
        unpack2(acc[r][1], v.z, v.w);
        *(float4*)&outp[(row0 + ty * 4 + r) * EMBD + tx * 4] = v;
    }
}

// ---------------- K3: reduce split-K + bias + relu, input embedding, build X ----------------
__global__ __launch_bounds__(128) void fuse_mid_kernel(const float* __restrict__ xabs,
                                                       const float* __restrict__ h0,
                                                       const float* __restrict__ W_emb,
                                                       const float* __restrict__ b_emb,
                                                       const float* __restrict__ b_soc) {
    const int n = blockIdx.x;
    const int t = threadIdx.x;
    if (t < 64) {
        float s = 0.0f;
        #pragma unroll
        for (int sp = 0; sp < KSPLIT; sp++) s += g_part[sp * (NP * EMBD) + n * EMBD + t];
        s += b_soc[t];
        g_X[n * KX + 64 + t] = fmaxf(s, 0.0f);

        const float x0 = xabs[2 * n], x1 = xabs[2 * n + 1];
        const float e = x0 * W_emb[2 * t] + x1 * W_emb[2 * t + 1] + b_emb[t];
        g_X[n * KX + t] = fmaxf(e, 0.0f);
    }
    g_X[n * KX + 128 + t] = h0[n * HID + t];
}

// ---------------- K4: gates GEMM  gates = X @ [W_ih|W_hh]^T + b_ih + b_hh ----------------
// M=1024 (16 tiles), N=512 (8 tiles of 64), K=256.
__global__ __launch_bounds__(256) void gemm_gates_kernel(const float* __restrict__ W_ih,
                                                         const float* __restrict__ W_hh,
                                                         const float* __restrict__ b_ih,
                                                         const float* __restrict__ b_hh) {
    __shared__ __align__(16) float As[64][33];
    __shared__ __align__(16) float Bs[32][66];

    const int row0 = blockIdx.x * 64;
    const int col0 = blockIdx.y * 64;
    const int t  = threadIdx.x;
    const int tx = t & 15;
    const int ty = t >> 4;

    ull acc[4][2];
    #pragma unroll
    for (int r = 0; r < 4; r++) { acc[r][0] = pack2(0.f, 0.f); acc[r][1] = pack2(0.f, 0.f); }

    for (int s = 0; s < KX / 32; s++) {
        const int k0 = s * 32;
        #pragma unroll
        for (int i = 0; i < 8; i++) {
            const int idx = t + i * 256;
            const int mm = idx >> 5, kk = idx & 31;
            As[mm][kk] = g_X[(row0 + mm) * KX + k0 + kk];
        }
        #pragma unroll
        for (int i = 0; i < 8; i++) {
            const int idx = t + i * 256;
            const int ee = idx >> 5, kk = idx & 31;
            const int gk = k0 + kk;
            const int g  = col0 + ee;
            Bs[kk][ee] = (gk < 128) ? W_ih[g * 128 + gk] : W_hh[g * 128 + (gk - 128)];
        }
        __syncthreads();

        #pragma unroll
        for (int kk = 0; kk < 32; kk++) {
            const ull b01 = *(const ull*)&Bs[kk][tx * 4];
            const ull b23 = *(const ull*)&Bs[kk][tx * 4 + 2];
            #pragma unroll
            for (int r = 0; r < 4; r++) {
                const float a  = As[ty * 4 + r][kk];
                const ull   a2 = pack2(a, a);
                acc[r][0] = fma2(a2, b01, acc[r][0]);
                acc[r][1] = fma2(a2, b23, acc[r][1]);
            }
        }
        __syncthreads();
    }

    const int gbase = col0 + tx * 4;
    const float4 bi = *(const float4*)&b_ih[gbase];
    const float4 bh = *(const float4*)&b_hh[gbase];
    #pragma unroll
    for (int r = 0; r < 4; r++) {
        float4 v;
        unpack2(acc[r][0], v.x, v.y);
        unpack2(acc[r][1], v.z, v.w);
        v.x += bi.x + bh.x; v.y += bi.y + bh.y;
        v.z += bi.z + bh.z; v.w += bi.w + bh.w;
        *(float4*)&g_gates[(row0 + ty * 4 + r) * NGATE + gbase] = v;
    }
}

// ---------------- K5: LSTM cell elementwise ----------------
__global__ __launch_bounds__(256) void lstm_kernel(const float* __restrict__ c0) {
    const int idx = blockIdx.x * 256 + threadIdx.x;   // NP*HID = 131072 total
    const int n = idx >> 7;
    const int d = idx & 127;
    const float* g = g_gates + n * NGATE;
    const float ig = g[d];
    const float fg = g[128 + d];
    const float gg = g[256 + d];
    const float og = g[384 + d];
    const float c = sigm(fg) * c0[idx] + sigm(ig) * tanhf(gg);
    g_h[idx] = sigm(og) * tanhf(c);
}

// ---------------- K6: output projection + MDN split layout ----------------
// Block: 16 rows x 60 output cols (gridDim.y=2 halves). W_out tile staged in shared.
__global__ __launch_bounds__(256) void out_kernel(const float* __restrict__ W_out,
                                                  const float* __restrict__ b_out,
                                                  float* __restrict__ out) {
    __shared__ __align__(16) float s_w[60 * 132];   // padded rows (132) for conflict-free float4
    __shared__ __align__(16) float s_h[16 * 128];

    const int row0 = blockIdx.x * 16;
    const int e0   = blockIdx.y * 60;
    const int t    = threadIdx.x;

    for (int i = t; i < 60 * 128; i += 256) {
        const int ee = i >> 7, k = i & 127;
        s_w[ee * 132 + k] = W_out[(e0 + ee) * 128 + k];
    }
    for (int i = t; i < 16 * 128; i += 256) s_h[i] = g_h[row0 * 128 + i];
    __syncthreads();

    for (int idx = t; idx < 16 * 60; idx += 256) {
        const int r  = idx / 60;
        const int ee = idx % 60;
        const float4* wp = (const float4*)(s_w + ee * 132);
        const float4* hp = (const float4*)(s_h + r * 128);
        float sum = 0.0f;
        #pragma unroll
        for (int k = 0; k < 32; k++) {
            const float4 w = wp[k];
            const float4 h = hp[k];
            sum += w.x * h.x + w.y * h.y + w.z * h.z + w.w * h.w;
        }
        const int e = e0 + ee;
        sum += b_out[e];
        const int sidx = e / MIX;       // which of the 6 outputs
        const int j    = e % MIX;
        out[sidx * (NP * MIX) + (row0 + r) * MIX + j] = sum;
    }
}

// ---------------- launch ----------------
extern "C" void kernel_launch(void* const* d_in, const int* in_sizes, int n_in,
                              void* d_out, int out_size) {
    const float* xabs  = (const float*)d_in[0];
    const float* h0    = (const float*)d_in[1];   // [1,N,H]
    const float* c0    = (const float*)d_in[2];   // [1,N,H]
    const float* W_emb = (const float*)d_in[3];
    const float* b_emb = (const float*)d_in[4];
    const float* W_soc = (const float*)d_in[5];
    const float* b_soc = (const float*)d_in[6];
    const float* W_ih  = (const float*)d_in[7];
    const float* W_hh  = (const float*)d_in[8];
    const float* b_ih  = (const float*)d_in[9];
    const float* b_hh  = (const float*)d_in[10];
    const float* W_out = (const float*)d_in[11];
    const float* b_out = (const float*)d_in[12];
    float* out = (float*)d_out;

    social_kernel<<<NP, 128>>>(xabs, h0);
    gemm_social_kernel<<<dim3(16, KSPLIT), 256>>>(W_soc);
    fuse_mid_kernel<<<NP, 128>>>(xabs, h0, W_emb, b_emb, b_soc);
    gemm_gates_kernel<<<dim3(16, 8), 256>>>(W_ih, W_hh, b_ih, b_hh);
    lstm_kernel<<<(NP * HID) / 256, 256>>>(c0);
    out_kernel<<<dim3(NP / 16, 2), 256>>>(W_out, b_out, out);
}

// round 2
// speedup vs baseline: 2.5318x; 2.5318x over previous
#include <cuda_runtime.h>
#include <math.h>

typedef unsigned long long ull;

#define NP     1024
#define EMBD   64
#define HID    128
#define NCELL  64
#define NGATE  512
#define KX     256      // [emb(64) | pool(64) | h0(128)]
#define MIX    20

// ---------------- device scratch (static, no allocations) ----------------
__device__ float g_P[NP * NCELL * EMBD];   // 16 MB: P[m, c, e]
__device__ float g_X[NP * KX];             // 1 MB
__device__ float g_gates[NP * NGATE];      // 2 MB
__device__ float g_h[NP * HID];            // 0.5 MB

// ---------------- f32x2 packed-FMA helpers ----------------
__device__ __forceinline__ ull pack2(float lo, float hi) {
    ull r; asm("mov.b64 %0, {%1, %2};" : "=l"(r) : "f"(lo), "f"(hi)); return r;
}
__device__ __forceinline__ void unpack2(ull v, float& lo, float& hi) {
    asm("mov.b64 {%0, %1}, %2;" : "=f"(lo), "=f"(hi) : "l"(v));
}
__device__ __forceinline__ ull fma2(ull a, ull b, ull c) {
    ull d; asm("fma.rn.f32x2 %0, %1, %2, %3;" : "=l"(d) : "l"(a), "l"(b), "l"(c)); return d;
}
__device__ __forceinline__ float sigm(float x) { return 1.0f / (1.0f + expf(-x)); }

// ============ K1: P-GEMM  P[m, c, e] = h0[m,:] . W_soc[e, c*128 : c*128+128] ============
// M=1024 (16 tiles of 64), "N" = 64 cells * 64 e -> grid.y = cell, tile covers all e.
// K=128 in 2 chunks of 64. 256 threads, 4x4 outputs each (cols paired in f32x2).
__global__ __launch_bounds__(256) void gemm_P_kernel(const float* __restrict__ h0,
                                                     const float* __restrict__ Wsoc) {
    __shared__ __align__(16) float As[64][66];   // [k][m]
    __shared__ __align__(16) float Bs[64][66];   // [k][e]

    const int row0 = blockIdx.x * 64;
    const int c    = blockIdx.y;
    const int t  = threadIdx.x;
    const int tx = t & 15;
    const int ty = t >> 4;

    ull acc[4][2];
    #pragma unroll
    for (int r = 0; r < 4; r++) { acc[r][0] = pack2(0.f, 0.f); acc[r][1] = pack2(0.f, 0.f); }

    #pragma unroll
    for (int chunk = 0; chunk < 2; chunk++) {
        const int k0 = chunk * 64;
        #pragma unroll
        for (int i = 0; i < 16; i++) {
            const int idx = t + i * 256;
            const int mm = idx >> 6, kk = idx & 63;
            As[kk][mm] = h0[(row0 + mm) * HID + k0 + kk];
        }
        #pragma unroll
        for (int i = 0; i < 16; i++) {
            const int idx = t + i * 256;
            const int ee = idx >> 6, kk = idx & 63;
            Bs[kk][ee] = Wsoc[ee * (NCELL * HID) + c * HID + k0 + kk];
        }
        __syncthreads();

        #pragma unroll
        for (int kk = 0; kk < 64; kk++) {
            const ull b01 = *(const ull*)&Bs[kk][tx * 4];
            const ull b23 = *(const ull*)&Bs[kk][tx * 4 + 2];
            #pragma unroll
            for (int r = 0; r < 4; r++) {
                const float a  = As[kk][ty * 4 + r];
                const ull   a2 = pack2(a, a);
                acc[r][0] = fma2(a2, b01, acc[r][0]);
                acc[r][1] = fma2(a2, b23, acc[r][1]);
            }
        }
        __syncthreads();
    }

    #pragma unroll
    for (int r = 0; r < 4; r++) {
        float4 v;
        unpack2(acc[r][0], v.x, v.y);
        unpack2(acc[r][1], v.z, v.w);
        *(float4*)&g_P[(row0 + ty * 4 + r) * (NCELL * EMBD) + c * EMBD + tx * 4] = v;
    }
}

// ============ K2: pair gather + X assembly (one CTA per pedestrian n) ============
// pooling[n,e] = relu(b_soc[e] + sum over valid m of P[m, cell(n,m), e])
// Deterministic compaction via warp-0 ballot scan (fixed m order, no atomics).
__global__ __launch_bounds__(256) void scatter_kernel(const float* __restrict__ xabs,
                                                      const float* __restrict__ h0,
                                                      const float* __restrict__ W_emb,
                                                      const float* __restrict__ b_emb,
                                                      const float* __restrict__ b_soc) {
    __shared__ float sx[NP];
    __shared__ float sy[NP];
    __shared__ int   slist[NP];     // P row offsets of valid pairs
    __shared__ int   scount;
    __shared__ float sred[4][64];

    const int n = blockIdx.x;
    const int t = threadIdx.x;

    for (int i = t; i < NP; i += 256) {
        sx[i] = xabs[2 * i];
        sy[i] = xabs[2 * i + 1];
    }
    __syncthreads();

    // independent work: copy h0 into X, compute input embedding
    if (t < 128) {
        g_X[n * KX + 128 + t] = h0[n * HID + t];
    } else if (t < 192) {
        const int e2 = t - 128;
        const float x0 = sx[n], x1 = sy[n];
        const float e = x0 * W_emb[2 * e2] + x1 * W_emb[2 * e2 + 1] + b_emb[e2];
        g_X[n * KX + e2] = fmaxf(e, 0.0f);
    }

    // phase A: warp 0 builds the compacted valid-pair list (deterministic order)
    if (t < 32) {
        const float wl = sx[n] - 0.2f;
        const float bl = sy[n] - 0.2f;
        int base = 0;
        for (int j = 0; j < 32; j++) {
            const int m = j * 32 + t;
            const float dx = sx[m] - wl;
            const float dy = sy[m] - bl;
            int cell = -1;
            if (dx >= 0.0f && dx < 0.4f && dy >= 0.0f && dy < 0.4f && m != n) {
                const int cx = (int)floorf(__fmul_rn(__fdiv_rn(dx, 0.4f), 8.0f));
                const int cy = (int)floorf(__fmul_rn(__fdiv_rn(dy, 0.4f), 8.0f));
                if (cx >= 0 && cx < 8 && cy >= 0 && cy < 8) cell = cx + cy * 8;
            }
            const unsigned mask = __ballot_sync(0xFFFFFFFFu, cell >= 0);
            if (cell >= 0) {
                const int pos = base + __popc(mask & ((1u << t) - 1u));
                slist[pos] = m * (NCELL * EMBD) + cell * EMBD;
            }
            base += __popc(mask);
        }
        if (t == 0) scount = base;
    }
    __syncthreads();

    // phase B: gather-accumulate P rows; 4 m-slots x 64 e-threads
    const int slot = t >> 6;
    const int e    = t & 63;
    const int cnt  = scount;
    float acc = 0.0f;
    int i = slot;
    for (; i + 8 <= cnt; i += 8) {
        const float v0 = g_P[slist[i] + e];
        const float v1 = g_P[slist[i + 4] + e];
        acc += v0;
        acc += v1;
    }
    for (; i < cnt; i += 4) acc += g_P[slist[i] + e];
    sred[slot][e] = acc;
    __syncthreads();

    if (t < 64) {
        float s = sred[0][e] + sred[1][e] + sred[2][e] + sred[3][e] + b_soc[e];
        g_X[n * KX + 64 + e] = fmaxf(s, 0.0f);
    }
}

// ============ K3: gates GEMM  gates = X @ [W_ih | W_hh]^T + b_ih + b_hh ============
// M=1024 (32 tiles of 32), N=512 (8 tiles of 64), K=256 (4 chunks of 64). 256 CTAs.
__global__ __launch_bounds__(256) void gemm_gates_kernel(const float* __restrict__ W_ih,
                                                         const float* __restrict__ W_hh,
                                                         const float* __restrict__ b_ih,
                                                         const float* __restrict__ b_hh) {
    __shared__ __align__(16) float As[64][34];   // [k][m], 32 rows
    __shared__ __align__(16) float Bs[64][66];   // [k][g]

    const int row0 = blockIdx.x * 32;
    const int col0 = blockIdx.y * 64;
    const int t  = threadIdx.x;
    const int tx = t & 15;
    const int ty = t >> 4;   // 0..15, 2 rows each

    ull acc[2][2];
    #pragma unroll
    for (int r = 0; r < 2; r++) { acc[r][0] = pack2(0.f, 0.f); acc[r][1] = pack2(0.f, 0.f); }

    #pragma unroll
    for (int chunk = 0; chunk < 4; chunk++) {
        const int k0 = chunk * 64;
        #pragma unroll
        for (int i = 0; i < 8; i++) {
            const int idx = t + i * 256;
            const int mm = idx >> 6, kk = idx & 63;
            As[kk][mm] = g_X[(row0 + mm) * KX + k0 + kk];
        }
        #pragma unroll
        for (int i = 0; i < 16; i++) {
            const int idx = t + i * 256;
            const int ee = idx >> 6, kk = idx & 63;
            const int gk = k0 + kk;
            const int g  = col0 + ee;
            Bs[kk][ee] = (gk < 128) ? W_ih[g * 128 + gk] : W_hh[g * 128 + (gk - 128)];
        }
        __syncthreads();

        #pragma unroll
        for (int kk = 0; kk < 64; kk++) {
            const ull b01 = *(const ull*)&Bs[kk][tx * 4];
            const ull b23 = *(const ull*)&Bs[kk][tx * 4 + 2];
            #pragma unroll
            for (int r = 0; r < 2; r++) {
                const float a  = As[kk][ty * 2 + r];
                const ull   a2 = pack2(a, a);
                acc[r][0] = fma2(a2, b01, acc[r][0]);
                acc[r][1] = fma2(a2, b23, acc[r][1]);
            }
        }
        __syncthreads();
    }

    const int gbase = col0 + tx * 4;
    const float4 bi = *(const float4*)&b_ih[gbase];
    const float4 bh = *(const float4*)&b_hh[gbase];
    #pragma unroll
    for (int r = 0; r < 2; r++) {
        float4 v;
        unpack2(acc[r][0], v.x, v.y);
        unpack2(acc[r][1], v.z, v.w);
        v.x += bi.x + bh.x; v.y += bi.y + bh.y;
        v.z += bi.z + bh.z; v.w += bi.w + bh.w;
        *(float4*)&g_gates[(row0 + ty * 2 + r) * NGATE + gbase] = v;
    }
}

// ============ K4: LSTM cell elementwise ============
__global__ __launch_bounds__(256) void lstm_kernel(const float* __restrict__ c0) {
    const int idx = blockIdx.x * 256 + threadIdx.x;   // NP*HID
    const int n = idx >> 7;
    const int d = idx & 127;
    const float* g = g_gates + n * NGATE;
    const float ig = g[d];
    const float fg = g[128 + d];
    const float gg = g[256 + d];
    const float og = g[384 + d];
    const float c = sigm(fg) * c0[idx] + sigm(ig) * tanhf(gg);
    g_h[idx] = sigm(og) * tanhf(c);
}

// ============ K5: output projection + MDN split layout ============
__global__ __launch_bounds__(256) void out_kernel(const float* __restrict__ W_out,
                                                  const float* __restrict__ b_out,
                                                  float* __restrict__ out) {
    __shared__ __align__(16) float s_w[60 * 132];
    __shared__ __align__(16) float s_h[16 * 128];

    const int row0 = blockIdx.x * 16;
    const int e0   = blockIdx.y * 60;
    const int t    = threadIdx.x;

    for (int i = t; i < 60 * 128; i += 256) {
        const int ee = i >> 7, k = i & 127;
        s_w[ee * 132 + k] = W_out[(e0 + ee) * 128 + k];
    }
    for (int i = t; i < 16 * 128; i += 256) s_h[i] = g_h[row0 * 128 + i];
    __syncthreads();

    for (int idx = t; idx < 16 * 60; idx += 256) {
        const int r  = idx / 60;
        const int ee = idx % 60;
        const float4* wp = (const float4*)(s_w + ee * 132);
        const float4* hp = (const float4*)(s_h + r * 128);
        float sum = 0.0f;
        #pragma unroll
        for (int k = 0; k < 32; k++) {
            const float4 w = wp[k];
            const float4 h = hp[k];
            sum += w.x * h.x + w.y * h.y + w.z * h.z + w.w * h.w;
        }
        const int e = e0 + ee;
        sum += b_out[e];
        const int sidx = e / MIX;
        const int j    = e % MIX;
        out[sidx * (NP * MIX) + (row0 + r) * MIX + j] = sum;
    }
}

// ---------------- launch ----------------
extern "C" void kernel_launch(void* const* d_in, const int* in_sizes, int n_in,
                              void* d_out, int out_size) {
    const float* xabs  = (const float*)d_in[0];
    const float* h0    = (const float*)d_in[1];
    const float* c0    = (const float*)d_in[2];
    const float* W_emb = (const float*)d_in[3];
    const float* b_emb = (const float*)d_in[4];
    const float* W_soc = (const float*)d_in[5];
    const float* b_soc = (const float*)d_in[6];
    const float* W_ih  = (const float*)d_in[7];
    const float* W_hh  = (const float*)d_in[8];
    const float* b_ih  = (const float*)d_in[9];
    const float* b_hh  = (const float*)d_in[10];
    const float* W_out = (const float*)d_in[11];
    const float* b_out = (const float*)d_in[12];
    float* out = (float*)d_out;

    gemm_P_kernel<<<dim3(16, 64), 256>>>(h0, W_soc);
    scatter_kernel<<<NP, 256>>>(xabs, h0, W_emb, b_emb, b_soc);
    gemm_gates_kernel<<<dim3(32, 8), 256>>>(W_ih, W_hh, b_ih, b_hh);
    lstm_kernel<<<(NP * HID) / 256, 256>>>(c0);
    out_kernel<<<dim3(NP / 16, 2), 256>>>(W_out, b_out, out);
}

// round 4
// speedup vs baseline: 3.6213x; 1.4303x over previous
#include <cuda_runtime.h>
#include <cuda_bf16.h>
#include <mma.h>
#include <math.h>
#include <stdint.h>

using namespace nvcuda;

typedef unsigned long long ull;

#define NP     1024
#define EMBD   64
#define HID    128
#define NCELL  64
#define PN     4096     // NCELL * EMBD
#define KX     256      // [emb(64) | pool(64) | h0(128)]
#define MIX    20

// ---------------- device scratch (static, no allocations) ----------------
__device__ float          g_P[NP * PN];        // 16 MB: P[m, c*64+e]
__device__ float          g_X[NP * KX];        // 1 MB
__device__ float          g_h[NP * HID];       // 0.5 MB
__device__ __nv_bfloat16  g_A1[NP * HID];
__device__ __nv_bfloat16  g_A2[NP * HID];
__device__ __nv_bfloat16  g_B1[PN * HID];
__device__ __nv_bfloat16  g_B2[PN * HID];

// ---------------- f32x2 packed-FMA helpers ----------------
__device__ __forceinline__ ull pack2(float lo, float hi) {
    ull r; asm("mov.b64 %0, {%1, %2};" : "=l"(r) : "f"(lo), "f"(hi)); return r;
}
__device__ __forceinline__ void unpack2(ull v, float& lo, float& hi) {
    asm("mov.b64 {%0, %1}, %2;" : "=f"(lo), "=f"(hi) : "l"(v));
}
__device__ __forceinline__ ull fma2(ull a, ull b, ull c) {
    ull d; asm("fma.rn.f32x2 %0, %1, %2, %3;" : "=l"(d) : "l"(a), "l"(b), "l"(c)); return d;
}
__device__ __forceinline__ float sigm(float x) { return 1.0f / (1.0f + expf(-x)); }

// ============ K0: bf16 splits (merged convA + convB) ============
// blocks [0,128): h0 -> A1/A2.  blocks [128,640): W_soc reindexed [c*64+e][k] -> B1/B2.
__global__ __launch_bounds__(256) void conv_kernel(const float* __restrict__ h0,
                                                   const float* __restrict__ Wsoc) {
    const int b = blockIdx.x;
    if (b < 128) {
        const int i4 = b * 256 + threadIdx.x;          // 32768 float4 chunks
        const float4 v = ((const float4*)h0)[i4];
        __nv_bfloat162 h1a, h1b, h2a, h2b;
        h1a.x = __float2bfloat16(v.x); h2a.x = __float2bfloat16(v.x - __bfloat162float(h1a.x));
        h1a.y = __float2bfloat16(v.y); h2a.y = __float2bfloat16(v.y - __bfloat162float(h1a.y));
        h1b.x = __float2bfloat16(v.z); h2b.x = __float2bfloat16(v.z - __bfloat162float(h1b.x));
        h1b.y = __float2bfloat16(v.w); h2b.y = __float2bfloat16(v.w - __bfloat162float(h1b.y));
        ((__nv_bfloat162*)g_A1)[i4 * 2]     = h1a;
        ((__nv_bfloat162*)g_A1)[i4 * 2 + 1] = h1b;
        ((__nv_bfloat162*)g_A2)[i4 * 2]     = h2a;
        ((__nv_bfloat162*)g_A2)[i4 * 2 + 1] = h2b;
    } else {
        const int i4 = (b - 128) * 256 + threadIdx.x;  // 131072 float4 chunks
        const int k4 = i4 & 31;
        const int ce = i4 >> 5;
        const int e  = ce & 63;
        const int c  = ce >> 6;
        const float4 v = *(const float4*)&Wsoc[e * (NCELL * HID) + c * HID + k4 * 4];
        __nv_bfloat162 h1a, h1b, h2a, h2b;
        h1a.x = __float2bfloat16(v.x); h2a.x = __float2bfloat16(v.x - __bfloat162float(h1a.x));
        h1a.y = __float2bfloat16(v.y); h2a.y = __float2bfloat16(v.y - __bfloat162float(h1a.y));
        h1b.x = __float2bfloat16(v.z); h2b.x = __float2bfloat16(v.z - __bfloat162float(h1b.x));
        h1b.y = __float2bfloat16(v.w); h2b.y = __float2bfloat16(v.w - __bfloat162float(h1b.y));
        ((__nv_bfloat162*)g_B1)[i4 * 2]     = h1a;
        ((__nv_bfloat162*)g_B1)[i4 * 2 + 1] = h1b;
        ((__nv_bfloat162*)g_B2)[i4 * 2]     = h2a;
        ((__nv_bfloat162*)g_B2)[i4 * 2 + 1] = h2b;
    }
}

// ============ K1: WMMA bf16 P-GEMM  P = A1@B1^T + A2@B1^T + A1@B2^T (fp32 acc) ============
// CTA tile 128x128, K=128 resident. 8 warps: 2 (m-halves of 64) x 4 (n-quarters of 32).
#define LDT 136                      // padded leading dim (bf16 elements), mult of 8
#define TILE_SMEM (128 * LDT)        // bf16 elements per tile
#define SMEM_MMA_BYTES (3 * TILE_SMEM * 2)

__device__ __forceinline__ void load_tile_bf16(__nv_bfloat16* dst,
                                               const __nv_bfloat16* __restrict__ src,
                                               int t) {
    // 128 rows x 128 bf16 (row-major, 256B rows) -> smem [row][k] with ld=LDT
    #pragma unroll
    for (int i = t; i < 2048; i += 256) {          // 16B chunks
        const int row = i >> 4;
        const int kc  = i & 15;
        *(uint4*)&dst[row * LDT + kc * 8] = ((const uint4*)src)[i];
    }
}

__global__ __launch_bounds__(256, 1) void mma_P_kernel() {
    extern __shared__ __align__(16) __nv_bfloat16 smem[];
    __nv_bfloat16* sA1 = smem;
    __nv_bfloat16* sA2 = smem + TILE_SMEM;
    __nv_bfloat16* sB  = smem + 2 * TILE_SMEM;

    const int t   = threadIdx.x;
    const int wid = t >> 5;
    const int warp_m = wid & 1;      // 0..1 : 64-row half
    const int warp_n = wid >> 1;     // 0..3 : 32-col quarter
    const int row0 = blockIdx.x * 128;
    const int col0 = blockIdx.y * 128;

    load_tile_bf16(sA1, g_A1 + row0 * HID, t);
    load_tile_bf16(sA2, g_A2 + row0 * HID, t);
    load_tile_bf16(sB,  g_B1 + col0 * HID, t);
    __syncthreads();

    wmma::fragment<wmma::accumulator, 16, 16, 16, float> acc[4][2];
    #pragma unroll
    for (int i = 0; i < 4; i++)
        #pragma unroll
        for (int j = 0; j < 2; j++)
            wmma::fill_fragment(acc[i][j], 0.0f);

    wmma::fragment<wmma::matrix_a, 16, 16, 16, __nv_bfloat16, wmma::row_major> af;
    wmma::fragment<wmma::matrix_b, 16, 16, 16, __nv_bfloat16, wmma::col_major> bf[2];

    // terms with B1: A1@B1 and A2@B1
    #pragma unroll
    for (int term = 0; term < 2; term++) {
        const __nv_bfloat16* sA = (term == 0) ? sA1 : sA2;
        #pragma unroll
        for (int k0 = 0; k0 < 8; k0++) {
            #pragma unroll
            for (int j = 0; j < 2; j++)
                wmma::load_matrix_sync(bf[j], sB + (warp_n * 32 + j * 16) * LDT + k0 * 16, LDT);
            #pragma unroll
            for (int i = 0; i < 4; i++) {
                wmma::load_matrix_sync(af, sA + (warp_m * 64 + i * 16) * LDT + k0 * 16, LDT);
                wmma::mma_sync(acc[i][0], af, bf[0], acc[i][0]);
                wmma::mma_sync(acc[i][1], af, bf[1], acc[i][1]);
            }
        }
    }
    __syncthreads();
    load_tile_bf16(sB, g_B2 + col0 * HID, t);
    __syncthreads();

    // term A1@B2
    #pragma unroll
    for (int k0 = 0; k0 < 8; k0++) {
        #pragma unroll
        for (int j = 0; j < 2; j++)
            wmma::load_matrix_sync(bf[j], sB + (warp_n * 32 + j * 16) * LDT + k0 * 16, LDT);
        #pragma unroll
        for (int i = 0; i < 4; i++) {
            wmma::load_matrix_sync(af, sA1 + (warp_m * 64 + i * 16) * LDT + k0 * 16, LDT);
            wmma::mma_sync(acc[i][0], af, bf[0], acc[i][0]);
            wmma::mma_sync(acc[i][1], af, bf[1], acc[i][1]);
        }
    }

    #pragma unroll
    for (int i = 0; i < 4; i++)
        #pragma unroll
        for (int j = 0; j < 2; j++) {
            float* dst = g_P + (size_t)(row0 + warp_m * 64 + i * 16) * PN
                             + col0 + warp_n * 32 + j * 16;
            wmma::store_matrix_sync(dst, acc[i][j], PN, wmma::mem_row_major);
        }
}

// ============ K2: pair gather + X assembly (one CTA per pedestrian n) ============
__global__ __launch_bounds__(256) void scatter_kernel(const float* __restrict__ xabs,
                                                      const float* __restrict__ h0,
                                                      const float* __restrict__ W_emb,
                                                      const float* __restrict__ b_emb,
                                                      const float* __restrict__ b_soc) {
    __shared__ float sx[NP];
    __shared__ float sy[NP];
    __shared__ int   slist[NP];
    __shared__ int   wcnt[8];
    __shared__ float sred[4][64];

    const int n = blockIdx.x;
    const int t = threadIdx.x;
    const int w = t >> 5;
    const int lane = t & 31;

    for (int i = t; i < NP; i += 256) {
        const float2 v = ((const float2*)xabs)[i];
        sx[i] = v.x;
        sy[i] = v.y;
    }
    __syncthreads();

    const float wl = sx[n] - 0.2f;
    const float bl = sy[n] - 0.2f;

    // phase A pass 1: every warp classifies its 128 m's (4 ballots)
    int cells[4];
    unsigned masks[4];
    int cnt = 0;
    #pragma unroll
    for (int j = 0; j < 4; j++) {
        const int m = w * 128 + j * 32 + lane;
        const float dx = sx[m] - wl;
        const float dy = sy[m] - bl;
        int cell = -1;
        if (dx >= 0.0f && dx < 0.4f && dy >= 0.0f && dy < 0.4f && m != n) {
            const int cx = (int)floorf(__fmul_rn(__fdiv_rn(dx, 0.4f), 8.0f));
            const int cy = (int)floorf(__fmul_rn(__fdiv_rn(dy, 0.4f), 8.0f));
            if (cx >= 0 && cx < 8 && cy >= 0 && cy < 8) cell = cx + cy * 8;
        }
        cells[j] = (cell >= 0) ? (m * PN + cell * EMBD) : -1;
        masks[j] = __ballot_sync(0xFFFFFFFFu, cell >= 0);
        cnt += __popc(masks[j]);
    }
    if (lane == 0) wcnt[w] = cnt;

    // independent work while counts settle
    if (t < 128) {
        g_X[n * KX + 128 + t] = h0[n * HID + t];
    } else if (t < 192) {
        const int e2 = t - 128;
        const float e = sx[n] * W_emb[2 * e2] + sy[n] * W_emb[2 * e2 + 1] + b_emb[e2];
        g_X[n * KX + e2] = fmaxf(e, 0.0f);
    }
    __syncthreads();

    // phase A pass 2: prefix over warps, write compacted list (m-ascending)
    int base = 0, tot = 0;
    #pragma unroll
    for (int ww = 0; ww < 8; ww++) {
        if (ww < w) base += wcnt[ww];
        tot += wcnt[ww];
    }
    #pragma unroll
    for (int j = 0; j < 4; j++) {
        if (cells[j] >= 0) {
            slist[base + __popc(masks[j] & ((1u << lane) - 1u))] = cells[j];
        }
        base += __popc(masks[j]);
    }
    __syncthreads();

    // phase B: gather-accumulate P rows; 4 m-slots x 64 e-threads
    const int slot = t >> 6;
    const int e    = t & 63;
    float acc = 0.0f;
    int i = slot;
    for (; i + 8 <= tot; i += 8) {
        acc += g_P[(size_t)slist[i] + e];
        acc += g_P[(size_t)slist[i + 4] + e];
    }
    for (; i < tot; i += 4) acc += g_P[(size_t)slist[i] + e];
    sred[slot][e] = acc;
    __syncthreads();

    if (t < 64) {
        const float s = sred[0][e] + sred[1][e] + sred[2][e] + sred[3][e] + b_soc[e];
        g_X[n * KX + 64 + e] = fmaxf(s, 0.0f);
    }
}

// ============ K3: gates GEMM fused with LSTM cell ============
// Tile: 32 rows x (4 gates x 16 d) = 64 cols, epilogue owns i,f,g,o for each (n,d).
__global__ __launch_bounds__(256) void gates_lstm_kernel(const float* __restrict__ W_ih,
                                                         const float* __restrict__ W_hh,
                                                         const float* __restrict__ b_ih,
                                                         const float* __restrict__ b_hh,
                                                         const float* __restrict__ c0) {
    __shared__ __align__(16) float As[64][34];   // [k][m]
    __shared__ __align__(16) float Bs[64][68];   // [k][cc]
    __shared__ float sg[32][68];                 // gates staging

    const int row0 = blockIdx.x * 32;
    const int d0   = blockIdx.y * 16;
    const int t  = threadIdx.x;
    const int tx = t & 15;
    const int ty = t >> 4;

    ull acc[2][2];
    #pragma unroll
    for (int r = 0; r < 2; r++) { acc[r][0] = pack2(0.f, 0.f); acc[r][1] = pack2(0.f, 0.f); }

    #pragma unroll
    for (int chunk = 0; chunk < 4; chunk++) {
        const int k0 = chunk * 64;
        #pragma unroll
        for (int i = 0; i < 8; i++) {
            const int idx = t + i * 256;
            const int mm = idx >> 6, kk = idx & 63;
            As[kk][mm] = g_X[(row0 + mm) * KX + k0 + kk];
        }
        #pragma unroll
        for (int i = 0; i < 16; i++) {
            const int idx = t + i * 256;
            const int cc = idx >> 6, kk = idx & 63;
            const int wrow = (cc >> 4) * 128 + d0 + (cc & 15);
            const int gk = k0 + kk;
            Bs[kk][cc] = (gk < 128) ? W_ih[wrow * 128 + gk] : W_hh[wrow * 128 + (gk - 128)];
        }
        __syncthreads();

        #pragma unroll
        for (int kk = 0; kk < 64; kk++) {
            const ull b01 = *(const ull*)&Bs[kk][tx * 4];
            const ull b23 = *(const ull*)&Bs[kk][tx * 4 + 2];
            #pragma unroll
            for (int r = 0; r < 2; r++) {
                const float a  = As[kk][ty * 2 + r];
                const ull   a2 = pack2(a, a);
                acc[r][0] = fma2(a2, b01, acc[r][0]);
                acc[r][1] = fma2(a2, b23, acc[r][1]);
            }
        }
        __syncthreads();
    }

    // bias + stage gates into shared
    const int gate = tx >> 2;
    const int dd4  = (tx & 3) * 4;
    const float4 bi4 = *(const float4*)&b_ih[gate * 128 + d0 + dd4];
    const float4 bh4 = *(const float4*)&b_hh[gate * 128 + d0 + dd4];
    #pragma unroll
    for (int r = 0; r < 2; r++) {
        float x, y, z, w;
        unpack2(acc[r][0], x, y);
        unpack2(acc[r][1], z, w);
        float* sp = &sg[ty * 2 + r][tx * 4];
        sp[0] = x + bi4.x + bh4.x;
        sp[1] = y + bi4.y + bh4.y;
        sp[2] = z + bi4.z + bh4.z;
        sp[3] = w + bi4.w + bh4.w;
    }
    __syncthreads();

    // LSTM cell for 32 rows x 16 d
    #pragma unroll
    for (int idx = t; idx < 512; idx += 256) {
        const int rl = idx >> 4;
        const int dd = idx & 15;
        const float ig = sg[rl][dd];
        const float fg = sg[rl][16 + dd];
        const float gg = sg[rl][32 + dd];
        const float og = sg[rl][48 + dd];
        const int n = row0 + rl;
        const int d = d0 + dd;
        const float c = sigm(fg) * c0[n * HID + d] + sigm(ig) * tanhf(gg);
        g_h[n * HID + d] = sigm(og) * tanhf(c);
    }
}

// ============ K4: output projection + MDN split layout ============
__global__ __launch_bounds__(256) void out_kernel(const float* __restrict__ W_out,
                                                  const float* __restrict__ b_out,
                                                  float* __restrict__ out) {
    __shared__ __align__(16) float s_w[60 * 132];
    __shared__ __align__(16) float s_h[16 * 128];

    const int row0 = blockIdx.x * 16;
    const int e0   = blockIdx.y * 60;
    const int t    = threadIdx.x;

    for (int i = t; i < 60 * 128; i += 256) {
        const int ee = i >> 7, k = i & 127;
        s_w[ee * 132 + k] = W_out[(e0 + ee) * 128 + k];
    }
    for (int i = t; i < 16 * 128; i += 256) s_h[i] = g_h[row0 * 128 + i];
    __syncthreads();

    for (int idx = t; idx < 16 * 60; idx += 256) {
        const int r  = idx / 60;
        const int ee = idx % 60;
        const float4* wp = (const float4*)(s_w + ee * 132);
        const float4* hp = (const float4*)(s_h + r * 128);
        float sum = 0.0f;
        #pragma unroll
        for (int k = 0; k < 32; k++) {
            const float4 w = wp[k];
            const float4 h = hp[k];
            sum += w.x * h.x + w.y * h.y + w.z * h.z + w.w * h.w;
        }
        const int e = e0 + ee;
        sum += b_out[e];
        out[(e / MIX) * (NP * MIX) + (row0 + r) * MIX + (e % MIX)] = sum;
    }
}

// ---------------- launch ----------------
extern "C" void kernel_launch(void* const* d_in, const int* in_sizes, int n_in,
                              void* d_out, int out_size) {
    const float* xabs  = (const float*)d_in[0];
    const float* h0    = (const float*)d_in[1];
    const float* c0    = (const float*)d_in[2];
    const float* W_emb = (const float*)d_in[3];
    const float* b_emb = (const float*)d_in[4];
    const float* W_soc = (const float*)d_in[5];
    const float* b_soc = (const float*)d_in[6];
    const float* W_ih  = (const float*)d_in[7];
    const float* W_hh  = (const float*)d_in[8];
    const float* b_ih  = (const float*)d_in[9];
    const float* b_hh  = (const float*)d_in[10];
    const float* W_out = (const float*)d_in[11];
    const float* b_out = (const float*)d_in[12];
    float* out = (float*)d_out;

    cudaFuncSetAttribute(mma_P_kernel, cudaFuncAttributeMaxDynamicSharedMemorySize, SMEM_MMA_BYTES);

    conv_kernel<<<640, 256>>>(h0, W_soc);
    mma_P_kernel<<<dim3(8, 32), 256, SMEM_MMA_BYTES>>>();
    scatter_kernel<<<NP, 256>>>(xabs, h0, W_emb, b_emb, b_soc);
    gates_lstm_kernel<<<dim3(32, 8), 256>>>(W_ih, W_hh, b_ih, b_hh, c0);
    out_kernel<<<dim3(NP / 16, 2), 256>>>(W_out, b_out, out);
}

// round 5
// speedup vs baseline: 4.2818x; 1.1824x over previous
#include <cuda_runtime.h>
#include <cuda_bf16.h>
#include <mma.h>
#include <math.h>
#include <stdint.h>

using namespace nvcuda;

typedef unsigned long long ull;

#define NP     1024
#define EMBD   64
#define HID    128
#define NCELL  64
#define PN     4096     // NCELL * EMBD
#define KX     256      // [emb(64) | pool(64) | h0(128)]
#define MIX    20

// ---------------- device scratch (static, no allocations) ----------------
__device__ float g_P[NP * PN];        // 16 MB: P[m, c*64+e]
__device__ float g_X[NP * KX];        // 1 MB
__device__ float g_h[NP * HID];       // 0.5 MB

__device__ __forceinline__ float sigm(float x) { return 1.0f / (1.0f + expf(-x)); }

// split one float4 into hi/lo bf16x2 pairs and store to smem
__device__ __forceinline__ void split_store(__nv_bfloat16* d1, __nv_bfloat16* d2, float4 v) {
    __nv_bfloat162 h1a, h1b, h2a, h2b;
    h1a.x = __float2bfloat16(v.x); h2a.x = __float2bfloat16(v.x - __bfloat162float(h1a.x));
    h1a.y = __float2bfloat16(v.y); h2a.y = __float2bfloat16(v.y - __bfloat162float(h1a.y));
    h1b.x = __float2bfloat16(v.z); h2b.x = __float2bfloat16(v.z - __bfloat162float(h1b.x));
    h1b.y = __float2bfloat16(v.w); h2b.y = __float2bfloat16(v.w - __bfloat162float(h1b.y));
    *(__nv_bfloat162*)(d1)     = h1a;
    *(__nv_bfloat162*)(d1 + 2) = h1b;
    *(__nv_bfloat162*)(d2)     = h2a;
    *(__nv_bfloat162*)(d2 + 2) = h2b;
}

// ============ K1: WMMA bf16 P-GEMM with in-kernel fp32->bf16 split ============
// P = A1@B1^T + A2@B1^T + A1@B2^T, fp32 acc. CTA tile 128x128, K=128 resident.
#define LDP 136
#define TILEP (128 * LDP)
#define SMEM_P_BYTES (4 * TILEP * 2)

__global__ __launch_bounds__(256, 1) void mma_P_kernel(const float* __restrict__ h0,
                                                       const float* __restrict__ Wsoc) {
    extern __shared__ __align__(16) __nv_bfloat16 smemP[];
    __nv_bfloat16* sA1 = smemP;
    __nv_bfloat16* sA2 = smemP + TILEP;
    __nv_bfloat16* sB1 = smemP + 2 * TILEP;
    __nv_bfloat16* sB2 = smemP + 3 * TILEP;

    const int t   = threadIdx.x;
    const int wid = t >> 5;
    const int warp_m = wid & 1;      // 64-row half
    const int warp_n = wid >> 1;     // 32-col quarter
    const int row0 = blockIdx.x * 128;
    const int col0 = blockIdx.y * 128;

    // load + split A (h0 tile) : 128 rows x 32 float4
    #pragma unroll
    for (int i = t; i < 4096; i += 256) {
        const int row = i >> 5, k4 = i & 31;
        const float4 v = *(const float4*)&h0[(row0 + row) * HID + k4 * 4];
        split_store(sA1 + row * LDP + k4 * 4, sA2 + row * LDP + k4 * 4, v);
    }
    // load + split B (W_soc reindexed [ce][k])
    #pragma unroll
    for (int i = t; i < 4096; i += 256) {
        const int row = i >> 5, k4 = i & 31;
        const int ce = col0 + row;
        const int e = ce & 63, c = ce >> 6;
        const float4 v = *(const float4*)&Wsoc[e * (NCELL * HID) + c * HID + k4 * 4];
        split_store(sB1 + row * LDP + k4 * 4, sB2 + row * LDP + k4 * 4, v);
    }
    __syncthreads();

    wmma::fragment<wmma::accumulator, 16, 16, 16, float> acc[4][2];
    #pragma unroll
    for (int i = 0; i < 4; i++)
        #pragma unroll
        for (int j = 0; j < 2; j++)
            wmma::fill_fragment(acc[i][j], 0.0f);

    wmma::fragment<wmma::matrix_a, 16, 16, 16, __nv_bfloat16, wmma::row_major> af;
    wmma::fragment<wmma::matrix_b, 16, 16, 16, __nv_bfloat16, wmma::col_major> bf[2];

    #pragma unroll
    for (int term = 0; term < 3; term++) {
        const __nv_bfloat16* sA = (term == 1) ? sA2 : sA1;
        const __nv_bfloat16* sB = (term == 2) ? sB2 : sB1;
        #pragma unroll
        for (int k0 = 0; k0 < 8; k0++) {
            #pragma unroll
            for (int j = 0; j < 2; j++)
                wmma::load_matrix_sync(bf[j], sB + (warp_n * 32 + j * 16) * LDP + k0 * 16, LDP);
            #pragma unroll
            for (int i = 0; i < 4; i++) {
                wmma::load_matrix_sync(af, sA + (warp_m * 64 + i * 16) * LDP + k0 * 16, LDP);
                wmma::mma_sync(acc[i][0], af, bf[0], acc[i][0]);
                wmma::mma_sync(acc[i][1], af, bf[1], acc[i][1]);
            }
        }
    }

    #pragma unroll
    for (int i = 0; i < 4; i++)
        #pragma unroll
        for (int j = 0; j < 2; j++) {
            float* dst = g_P + (size_t)(row0 + warp_m * 64 + i * 16) * PN
                             + col0 + warp_n * 32 + j * 16;
            wmma::store_matrix_sync(dst, acc[i][j], PN, wmma::mem_row_major);
        }
}

// ============ K2: pair gather + X assembly (512 threads per pedestrian n) ============
__global__ __launch_bounds__(512) void scatter_kernel(const float* __restrict__ xabs,
                                                      const float* __restrict__ h0,
                                                      const float* __restrict__ W_emb,
                                                      const float* __restrict__ b_emb,
                                                      const float* __restrict__ b_soc) {
    __shared__ float sx[NP];
    __shared__ float sy[NP];
    __shared__ int   slist[NP];
    __shared__ int   wcnt[16];
    __shared__ float sred[8][64];

    const int n = blockIdx.x;
    const int t = threadIdx.x;
    const int w = t >> 5;
    const int lane = t & 31;

    for (int i = t; i < NP; i += 512) {
        const float2 v = ((const float2*)xabs)[i];
        sx[i] = v.x;
        sy[i] = v.y;
    }
    __syncthreads();

    const float wl = sx[n] - 0.2f;
    const float bl = sy[n] - 0.2f;

    // phase A pass 1: 16 warps classify 64 m's each (2 ballots)
    int cells[2];
    unsigned masks[2];
    int cnt = 0;
    #pragma unroll
    for (int j = 0; j < 2; j++) {
        const int m = w * 64 + j * 32 + lane;
        const float dx = sx[m] - wl;
        const float dy = sy[m] - bl;
        int cell = -1;
        if (dx >= 0.0f && dx < 0.4f && dy >= 0.0f && dy < 0.4f && m != n) {
            const int cx = (int)floorf(__fmul_rn(__fdiv_rn(dx, 0.4f), 8.0f));
            const int cy = (int)floorf(__fmul_rn(__fdiv_rn(dy, 0.4f), 8.0f));
            if (cx >= 0 && cx < 8 && cy >= 0 && cy < 8) cell = cx + cy * 8;
        }
        cells[j] = (cell >= 0) ? (m * PN + cell * EMBD) : -1;
        masks[j] = __ballot_sync(0xFFFFFFFFu, cell >= 0);
        cnt += __popc(masks[j]);
    }
    if (lane == 0) wcnt[w] = cnt;

    // independent work
    if (t < 128) {
        g_X[n * KX + 128 + t] = h0[n * HID + t];
    } else if (t < 192) {
        const int e2 = t - 128;
        const float e = sx[n] * W_emb[2 * e2] + sy[n] * W_emb[2 * e2 + 1] + b_emb[e2];
        g_X[n * KX + e2] = fmaxf(e, 0.0f);
    }
    __syncthreads();

    // phase A pass 2: prefix over warps, write compacted list (m-ascending)
    int base = 0, tot = 0;
    #pragma unroll
    for (int ww = 0; ww < 16; ww++) {
        if (ww < w) base += wcnt[ww];
        tot += wcnt[ww];
    }
    #pragma unroll
    for (int j = 0; j < 2; j++) {
        if (cells[j] >= 0) {
            slist[base + __popc(masks[j] & ((1u << lane) - 1u))] = cells[j];
        }
        base += __popc(masks[j]);
    }
    __syncthreads();

    // phase B: gather-accumulate P rows; 8 m-slots x 64 e-threads
    const int slot = t >> 6;
    const int e    = t & 63;
    float acc = 0.0f;
    int i = slot;
    for (; i + 16 <= tot; i += 16) {
        acc += g_P[(size_t)slist[i] + e];
        acc += g_P[(size_t)slist[i + 8] + e];
    }
    for (; i < tot; i += 8) acc += g_P[(size_t)slist[i] + e];
    sred[slot][e] = acc;
    __syncthreads();

    if (t < 64) {
        float s = b_soc[e];
        #pragma unroll
        for (int sl = 0; sl < 8; sl++) s += sred[sl][e];
        g_X[n * KX + 64 + e] = fmaxf(s, 0.0f);
    }
}

// ============ K3: WMMA gates GEMM fused with LSTM cell ============
// CTA tile 64 rows x 64 cols where cols = 4 gates x 16 d (d-slice d0..d0+15).
// In-kernel fp32->bf16 3-term split for both X and W.
#define LDG 264
#define TILEG (64 * LDG)
#define SMEM_G_BYTES (4 * TILEG * 2 + 64 * 68 * 4)

__global__ __launch_bounds__(256, 1) void gates_lstm_kernel(const float* __restrict__ W_ih,
                                                            const float* __restrict__ W_hh,
                                                            const float* __restrict__ b_ih,
                                                            const float* __restrict__ b_hh,
                                                            const float* __restrict__ c0) {
    extern __shared__ __align__(16) __nv_bfloat16 smemG[];
    __nv_bfloat16* sA1 = smemG;
    __nv_bfloat16* sA2 = smemG + TILEG;
    __nv_bfloat16* sB1 = smemG + 2 * TILEG;
    __nv_bfloat16* sB2 = smemG + 3 * TILEG;
    float* sg = (float*)(smemG + 4 * TILEG);   // [64][68]

    const int row0 = blockIdx.x * 64;
    const int d0   = blockIdx.y * 16;
    const int t   = threadIdx.x;
    const int wid = t >> 5;
    const int warp_m = wid & 3;      // 16-row block
    const int warp_n = wid >> 2;     // 32-col half

    // load + split X : 64 rows x 64 float4 (K=256)
    #pragma unroll
    for (int i = t; i < 4096; i += 256) {
        const int row = i >> 6, k4 = i & 63;
        const float4 v = *(const float4*)&g_X[(row0 + row) * KX + k4 * 4];
        split_store(sA1 + row * LDG + k4 * 4, sA2 + row * LDG + k4 * 4, v);
    }
    // load + split W : cc -> gate-major rows of [W_ih | W_hh]
    #pragma unroll
    for (int i = t; i < 4096; i += 256) {
        const int cc = i >> 6, k4 = i & 63;
        const int wrow = (cc >> 4) * 128 + d0 + (cc & 15);
        const float4 v = (k4 < 32) ? *(const float4*)&W_ih[wrow * 128 + k4 * 4]
                                   : *(const float4*)&W_hh[wrow * 128 + (k4 - 32) * 4];
        split_store(sB1 + cc * LDG + k4 * 4, sB2 + cc * LDG + k4 * 4, v);
    }
    __syncthreads();

    wmma::fragment<wmma::accumulator, 16, 16, 16, float> acc[2];
    wmma::fill_fragment(acc[0], 0.0f);
    wmma::fill_fragment(acc[1], 0.0f);

    wmma::fragment<wmma::matrix_a, 16, 16, 16, __nv_bfloat16, wmma::row_major> af;
    wmma::fragment<wmma::matrix_b, 16, 16, 16, __nv_bfloat16, wmma::col_major> bf[2];

    #pragma unroll
    for (int term = 0; term < 3; term++) {
        const __nv_bfloat16* sA = (term == 1) ? sA2 : sA1;
        const __nv_bfloat16* sB = (term == 2) ? sB2 : sB1;
        #pragma unroll
        for (int k0 = 0; k0 < 16; k0++) {
            wmma::load_matrix_sync(af, sA + (warp_m * 16) * LDG + k0 * 16, LDG);
            #pragma unroll
            for (int j = 0; j < 2; j++) {
                wmma::load_matrix_sync(bf[j], sB + (warp_n * 32 + j * 16) * LDG + k0 * 16, LDG);
                wmma::mma_sync(acc[j], af, bf[j], acc[j]);
            }
        }
    }

    #pragma unroll
    for (int j = 0; j < 2; j++)
        wmma::store_matrix_sync(sg + (warp_m * 16) * 68 + warp_n * 32 + j * 16,
                                acc[j], 68, wmma::mem_row_major);
    __syncthreads();

    // LSTM cell: 64 rows x 16 d
    #pragma unroll
    for (int idx = t; idx < 1024; idx += 256) {
        const int rl = idx >> 4;
        const int dd = idx & 15;
        const int d = d0 + dd;
        const float ig = sg[rl * 68 + dd]      + b_ih[d]       + b_hh[d];
        const float fg = sg[rl * 68 + 16 + dd] + b_ih[128 + d] + b_hh[128 + d];
        const float gg = sg[rl * 68 + 32 + dd] + b_ih[256 + d] + b_hh[256 + d];
        const float og = sg[rl * 68 + 48 + dd] + b_ih[384 + d] + b_hh[384 + d];
        const int n = row0 + rl;
        const float c = sigm(fg) * c0[n * HID + d] + sigm(ig) * tanhf(gg);
        g_h[n * HID + d] = sigm(og) * tanhf(c);
    }
}

// ============ K4: output projection + MDN split layout ============
__global__ __launch_bounds__(256) void out_kernel(const float* __restrict__ W_out,
                                                  const float* __restrict__ b_out,
                                                  float* __restrict__ out) {
    __shared__ __align__(16) float s_w[60 * 132];
    __shared__ __align__(16) float s_h[16 * 128];

    const int row0 = blockIdx.x * 16;
    const int e0   = blockIdx.y * 60;
    const int t    = threadIdx.x;

    for (int i = t; i < 60 * 128; i += 256) {
        const int ee = i >> 7, k = i & 127;
        s_w[ee * 132 + k] = W_out[(e0 + ee) * 128 + k];
    }
    for (int i = t; i < 16 * 128; i += 256) s_h[i] = g_h[row0 * 128 + i];
    __syncthreads();

    for (int idx = t; idx < 16 * 60; idx += 256) {
        const int r  = idx / 60;
        const int ee = idx % 60;
        const float4* wp = (const float4*)(s_w + ee * 132);
        const float4* hp = (const float4*)(s_h + r * 128);
        float sum = 0.0f;
        #pragma unroll
        for (int k = 0; k < 32; k++) {
            const float4 w = wp[k];
            const float4 h = hp[k];
            sum += w.x * h.x + w.y * h.y + w.z * h.z + w.w * h.w;
        }
        const int e = e0 + ee;
        sum += b_out[e];
        out[(e / MIX) * (NP * MIX) + (row0 + r) * MIX + (e % MIX)] = sum;
    }
}

// ---------------- launch ----------------
extern "C" void kernel_launch(void* const* d_in, const int* in_sizes, int n_in,
                              void* d_out, int out_size) {
    const float* xabs  = (const float*)d_in[0];
    const float* h0    = (const float*)d_in[1];
    const float* c0    = (const float*)d_in[2];
    const float* W_emb = (const float*)d_in[3];
    const float* b_emb = (const float*)d_in[4];
    const float* W_soc = (const float*)d_in[5];
    const float* b_soc = (const float*)d_in[6];
    const float* W_ih  = (const float*)d_in[7];
    const float* W_hh  = (const float*)d_in[8];
    const float* b_ih  = (const float*)d_in[9];
    const float* b_hh  = (const float*)d_in[10];
    const float* W_out = (const float*)d_in[11];
    const float* b_out = (const float*)d_in[12];
    float* out = (float*)d_out;

    cudaFuncSetAttribute(mma_P_kernel, cudaFuncAttributeMaxDynamicSharedMemorySize, SMEM_P_BYTES);
    cudaFuncSetAttribute(gates_lstm_kernel, cudaFuncAttributeMaxDynamicSharedMemorySize, SMEM_G_BYTES);

    mma_P_kernel<<<dim3(8, 32), 256, SMEM_P_BYTES>>>(h0, W_soc);
    scatter_kernel<<<NP, 512>>>(xabs, h0, W_emb, b_emb, b_soc);
    gates_lstm_kernel<<<dim3(16, 8), 256, SMEM_G_BYTES>>>(W_ih, W_hh, b_ih, b_hh, c0);
    out_kernel<<<dim3(NP / 16, 2), 256>>>(W_out, b_out, out);
}

// round 6
// speedup vs baseline: 4.5538x; 1.0635x over previous
#include <cuda_runtime.h>
#include <cuda_bf16.h>
#include <mma.h>
#include <math.h>
#include <stdint.h>

using namespace nvcuda;

typedef unsigned long long ull;

#define NP     1024
#define EMBD   64
#define HID    128
#define NCELL  64
#define PN     4096     // NCELL * EMBD
#define KX     256      // [emb(64) | pool(64) | h0(128)]
#define MIX    20
#define NOUT   120

// ---------------- device scratch (static, no allocations) ----------------
__device__ float g_P[NP * PN];        // 16 MB: P[m, c*64+e]
__device__ float g_X[NP * KX];        // 1 MB
__device__ float g_h[NP * HID];       // 0.5 MB

__device__ __forceinline__ float sigm(float x) { return 1.0f / (1.0f + expf(-x)); }

// split one float4 into hi/lo bf16x2 pairs and store to smem
__device__ __forceinline__ void split_store(__nv_bfloat16* d1, __nv_bfloat16* d2, float4 v) {
    __nv_bfloat162 h1a, h1b, h2a, h2b;
    h1a.x = __float2bfloat16(v.x); h2a.x = __float2bfloat16(v.x - __bfloat162float(h1a.x));
    h1a.y = __float2bfloat16(v.y); h2a.y = __float2bfloat16(v.y - __bfloat162float(h1a.y));
    h1b.x = __float2bfloat16(v.z); h2b.x = __float2bfloat16(v.z - __bfloat162float(h1b.x));
    h1b.y = __float2bfloat16(v.w); h2b.y = __float2bfloat16(v.w - __bfloat162float(h1b.y));
    *(__nv_bfloat162*)(d1)     = h1a;
    *(__nv_bfloat162*)(d1 + 2) = h1b;
    *(__nv_bfloat162*)(d2)     = h2a;
    *(__nv_bfloat162*)(d2 + 2) = h2b;
}

// ============ K1: WMMA bf16 P-GEMM with in-kernel fp32->bf16 split ============
// P = A1@B1^T + A2@B1^T + A1@B2^T, fp32 acc. CTA tile 128x128, K=128 resident.
#define LDP 136
#define TILEP (128 * LDP)
#define SMEM_P_BYTES (4 * TILEP * 2)

__global__ __launch_bounds__(256, 1) void mma_P_kernel(const float* __restrict__ h0,
                                                       const float* __restrict__ Wsoc) {
    extern __shared__ __align__(16) __nv_bfloat16 smemP[];
    __nv_bfloat16* sA1 = smemP;
    __nv_bfloat16* sA2 = smemP + TILEP;
    __nv_bfloat16* sB1 = smemP + 2 * TILEP;
    __nv_bfloat16* sB2 = smemP + 3 * TILEP;

    const int t   = threadIdx.x;
    const int wid = t >> 5;
    const int warp_m = wid & 1;      // 64-row half
    const int warp_n = wid >> 1;     // 32-col quarter
    const int row0 = blockIdx.x * 128;
    const int col0 = blockIdx.y * 128;

    #pragma unroll
    for (int i = t; i < 4096; i += 256) {
        const int row = i >> 5, k4 = i & 31;
        const float4 v = *(const float4*)&h0[(row0 + row) * HID + k4 * 4];
        split_store(sA1 + row * LDP + k4 * 4, sA2 + row * LDP + k4 * 4, v);
    }
    #pragma unroll
    for (int i = t; i < 4096; i += 256) {
        const int row = i >> 5, k4 = i & 31;
        const int ce = col0 + row;
        const int e = ce & 63, c = ce >> 6;
        const float4 v = *(const float4*)&Wsoc[e * (NCELL * HID) + c * HID + k4 * 4];
        split_store(sB1 + row * LDP + k4 * 4, sB2 + row * LDP + k4 * 4, v);
    }
    __syncthreads();

    wmma::fragment<wmma::accumulator, 16, 16, 16, float> acc[4][2];
    #pragma unroll
    for (int i = 0; i < 4; i++)
        #pragma unroll
        for (int j = 0; j < 2; j++)
            wmma::fill_fragment(acc[i][j], 0.0f);

    wmma::fragment<wmma::matrix_a, 16, 16, 16, __nv_bfloat16, wmma::row_major> af;
    wmma::fragment<wmma::matrix_b, 16, 16, 16, __nv_bfloat16, wmma::col_major> bf[2];

    #pragma unroll
    for (int term = 0; term < 3; term++) {
        const __nv_bfloat16* sA = (term == 1) ? sA2 : sA1;
        const __nv_bfloat16* sB = (term == 2) ? sB2 : sB1;
        #pragma unroll
        for (int k0 = 0; k0 < 8; k0++) {
            #pragma unroll
            for (int j = 0; j < 2; j++)
                wmma::load_matrix_sync(bf[j], sB + (warp_n * 32 + j * 16) * LDP + k0 * 16, LDP);
            #pragma unroll
            for (int i = 0; i < 4; i++) {
                wmma::load_matrix_sync(af, sA + (warp_m * 64 + i * 16) * LDP + k0 * 16, LDP);
                wmma::mma_sync(acc[i][0], af, bf[0], acc[i][0]);
                wmma::mma_sync(acc[i][1], af, bf[1], acc[i][1]);
            }
        }
    }

    #pragma unroll
    for (int i = 0; i < 4; i++)
        #pragma unroll
        for (int j = 0; j < 2; j++) {
            float* dst = g_P + (size_t)(row0 + warp_m * 64 + i * 16) * PN
                             + col0 + warp_n * 32 + j * 16;
            wmma::store_matrix_sync(dst, acc[i][j], PN, wmma::mem_row_major);
        }
}

// ============ K2: pair gather + X assembly (512 threads per pedestrian n) ============
__global__ __launch_bounds__(512) void scatter_kernel(const float* __restrict__ xabs,
                                                      const float* __restrict__ h0,
                                                      const float* __restrict__ W_emb,
                                                      const float* __restrict__ b_emb,
                                                      const float* __restrict__ b_soc) {
    __shared__ float sx[NP];
    __shared__ float sy[NP];
    __shared__ int   slist[NP];
    __shared__ int   wcnt[16];
    __shared__ float sred[8][64];

    const int n = blockIdx.x;
    const int t = threadIdx.x;
    const int w = t >> 5;
    const int lane = t & 31;

    for (int i = t; i < NP; i += 512) {
        const float2 v = ((const float2*)xabs)[i];
        sx[i] = v.x;
        sy[i] = v.y;
    }
    __syncthreads();

    const float wl = sx[n] - 0.2f;
    const float bl = sy[n] - 0.2f;

    int cells[2];
    unsigned masks[2];
    int cnt = 0;
    #pragma unroll
    for (int j = 0; j < 2; j++) {
        const int m = w * 64 + j * 32 + lane;
        const float dx = sx[m] - wl;
        const float dy = sy[m] - bl;
        int cell = -1;
        if (dx >= 0.0f && dx < 0.4f && dy >= 0.0f && dy < 0.4f && m != n) {
            const int cx = (int)floorf(__fmul_rn(__fdiv_rn(dx, 0.4f), 8.0f));
            const int cy = (int)floorf(__fmul_rn(__fdiv_rn(dy, 0.4f), 8.0f));
            if (cx >= 0 && cx < 8 && cy >= 0 && cy < 8) cell = cx + cy * 8;
        }
        cells[j] = (cell >= 0) ? (m * PN + cell * EMBD) : -1;
        masks[j] = __ballot_sync(0xFFFFFFFFu, cell >= 0);
        cnt += __popc(masks[j]);
    }
    if (lane == 0) wcnt[w] = cnt;

    if (t < 128) {
        g_X[n * KX + 128 + t] = h0[n * HID + t];
    } else if (t < 192) {
        const int e2 = t - 128;
        const float e = sx[n] * W_emb[2 * e2] + sy[n] * W_emb[2 * e2 + 1] + b_emb[e2];
        g_X[n * KX + e2] = fmaxf(e, 0.0f);
    }
    __syncthreads();

    int base = 0, tot = 0;
    #pragma unroll
    for (int ww = 0; ww < 16; ww++) {
        if (ww < w) base += wcnt[ww];
        tot += wcnt[ww];
    }
    #pragma unroll
    for (int j = 0; j < 2; j++) {
        if (cells[j] >= 0) {
            slist[base + __popc(masks[j] & ((1u << lane) - 1u))] = cells[j];
        }
        base += __popc(masks[j]);
    }
    __syncthreads();

    const int slot = t >> 6;
    const int e    = t & 63;
    float acc = 0.0f;
    int i = slot;
    for (; i + 16 <= tot; i += 16) {
        acc += g_P[(size_t)slist[i] + e];
        acc += g_P[(size_t)slist[i + 8] + e];
    }
    for (; i < tot; i += 8) acc += g_P[(size_t)slist[i] + e];
    sred[slot][e] = acc;
    __syncthreads();

    if (t < 64) {
        float s = b_soc[e];
        #pragma unroll
        for (int sl = 0; sl < 8; sl++) s += sred[sl][e];
        g_X[n * KX + 64 + e] = fmaxf(s, 0.0f);
    }
}

// ============ K3: WMMA gates GEMM fused with LSTM cell ============
#define LDG 264
#define TILEG (64 * LDG)
#define SMEM_G_BYTES (4 * TILEG * 2 + 64 * 68 * 4)

__global__ __launch_bounds__(256, 1) void gates_lstm_kernel(const float* __restrict__ W_ih,
                                                            const float* __restrict__ W_hh,
                                                            const float* __restrict__ b_ih,
                                                            const float* __restrict__ b_hh,
                                                            const float* __restrict__ c0) {
    extern __shared__ __align__(16) __nv_bfloat16 smemG[];
    __nv_bfloat16* sA1 = smemG;
    __nv_bfloat16* sA2 = smemG + TILEG;
    __nv_bfloat16* sB1 = smemG + 2 * TILEG;
    __nv_bfloat16* sB2 = smemG + 3 * TILEG;
    float* sg = (float*)(smemG + 4 * TILEG);   // [64][68]

    const int row0 = blockIdx.x * 64;
    const int d0   = blockIdx.y * 16;
    const int t   = threadIdx.x;
    const int wid = t >> 5;
    const int warp_m = wid & 3;
    const int warp_n = wid >> 2;

    #pragma unroll
    for (int i = t; i < 4096; i += 256) {
        const int row = i >> 6, k4 = i & 63;
        const float4 v = *(const float4*)&g_X[(row0 + row) * KX + k4 * 4];
        split_store(sA1 + row * LDG + k4 * 4, sA2 + row * LDG + k4 * 4, v);
    }
    #pragma unroll
    for (int i = t; i < 4096; i += 256) {
        const int cc = i >> 6, k4 = i & 63;
        const int wrow = (cc >> 4) * 128 + d0 + (cc & 15);
        const float4 v = (k4 < 32) ? *(const float4*)&W_ih[wrow * 128 + k4 * 4]
                                   : *(const float4*)&W_hh[wrow * 128 + (k4 - 32) * 4];
        split_store(sB1 + cc * LDG + k4 * 4, sB2 + cc * LDG + k4 * 4, v);
    }
    __syncthreads();

    wmma::fragment<wmma::accumulator, 16, 16, 16, float> acc[2];
    wmma::fill_fragment(acc[0], 0.0f);
    wmma::fill_fragment(acc[1], 0.0f);

    wmma::fragment<wmma::matrix_a, 16, 16, 16, __nv_bfloat16, wmma::row_major> af;
    wmma::fragment<wmma::matrix_b, 16, 16, 16, __nv_bfloat16, wmma::col_major> bf[2];

    #pragma unroll
    for (int term = 0; term < 3; term++) {
        const __nv_bfloat16* sA = (term == 1) ? sA2 : sA1;
        const __nv_bfloat16* sB = (term == 2) ? sB2 : sB1;
        #pragma unroll
        for (int k0 = 0; k0 < 16; k0++) {
            wmma::load_matrix_sync(af, sA + (warp_m * 16) * LDG + k0 * 16, LDG);
            #pragma unroll
            for (int j = 0; j < 2; j++) {
                wmma::load_matrix_sync(bf[j], sB + (warp_n * 32 + j * 16) * LDG + k0 * 16, LDG);
                wmma::mma_sync(acc[j], af, bf[j], acc[j]);
            }
        }
    }

    #pragma unroll
    for (int j = 0; j < 2; j++)
        wmma::store_matrix_sync(sg + (warp_m * 16) * 68 + warp_n * 32 + j * 16,
                                acc[j], 68, wmma::mem_row_major);
    __syncthreads();

    #pragma unroll
    for (int idx = t; idx < 1024; idx += 256) {
        const int rl = idx >> 4;
        const int dd = idx & 15;
        const int d = d0 + dd;
        const float ig = sg[rl * 68 + dd]      + b_ih[d]       + b_hh[d];
        const float fg = sg[rl * 68 + 16 + dd] + b_ih[128 + d] + b_hh[128 + d];
        const float gg = sg[rl * 68 + 32 + dd] + b_ih[256 + d] + b_hh[256 + d];
        const float og = sg[rl * 68 + 48 + dd] + b_ih[384 + d] + b_hh[384 + d];
        const int n = row0 + rl;
        const float c = sigm(fg) * c0[n * HID + d] + sigm(ig) * tanhf(gg);
        g_h[n * HID + d] = sigm(og) * tanhf(c);
    }
}

// ============ K4: WMMA output projection + MDN split layout ============
// CTA tile 32 rows x 128 cols (NOUT=120 padded), K=128 resident. 32 CTAs.
#define LDO 136
#define SMEM_O_BYTES ((2 * 32 * LDO + 2 * 128 * LDO) * 2 + 32 * 132 * 4)

__global__ __launch_bounds__(256, 1) void out_kernel(const float* __restrict__ W_out,
                                                     const float* __restrict__ b_out,
                                                     float* __restrict__ out) {
    extern __shared__ __align__(16) __nv_bfloat16 smemO[];
    __nv_bfloat16* sA1 = smemO;                      // 32 x LDO
    __nv_bfloat16* sA2 = smemO + 32 * LDO;
    __nv_bfloat16* sB1 = smemO + 2 * 32 * LDO;       // 128 x LDO
    __nv_bfloat16* sB2 = sB1 + 128 * LDO;
    float* so = (float*)(sB2 + 128 * LDO);           // [32][132]

    const int row0 = blockIdx.x * 32;
    const int t   = threadIdx.x;
    const int wid = t >> 5;
    const int warp_m = wid & 1;     // 16-row half
    const int warp_n = wid >> 1;    // 32-col quarter

    // load + split h tile: 32 rows x 32 float4
    #pragma unroll
    for (int i = t; i < 1024; i += 256) {
        const int row = i >> 5, k4 = i & 31;
        const float4 v = *(const float4*)&g_h[(row0 + row) * HID + k4 * 4];
        split_store(sA1 + row * LDO + k4 * 4, sA2 + row * LDO + k4 * 4, v);
    }
    // load + split W_out: 120 rows x 32 float4, pad rows 120..127 with zeros
    #pragma unroll
    for (int i = t; i < 4096; i += 256) {
        const int ee = i >> 5, k4 = i & 31;
        const float4 v = (ee < NOUT) ? *(const float4*)&W_out[ee * HID + k4 * 4]
                                     : make_float4(0.f, 0.f, 0.f, 0.f);
        split_store(sB1 + ee * LDO + k4 * 4, sB2 + ee * LDO + k4 * 4, v);
    }
    __syncthreads();

    wmma::fragment<wmma::accumulator, 16, 16, 16, float> acc[2];
    wmma::fill_fragment(acc[0], 0.0f);
    wmma::fill_fragment(acc[1], 0.0f);

    wmma::fragment<wmma::matrix_a, 16, 16, 16, __nv_bfloat16, wmma::row_major> af;
    wmma::fragment<wmma::matrix_b, 16, 16, 16, __nv_bfloat16, wmma::col_major> bf[2];

    #pragma unroll
    for (int term = 0; term < 3; term++) {
        const __nv_bfloat16* sA = (term == 1) ? sA2 : sA1;
        const __nv_bfloat16* sB = (term == 2) ? sB2 : sB1;
        #pragma unroll
        for (int k0 = 0; k0 < 8; k0++) {
            wmma::load_matrix_sync(af, sA + (warp_m * 16) * LDO + k0 * 16, LDO);
            #pragma unroll
            for (int j = 0; j < 2; j++) {
                wmma::load_matrix_sync(bf[j], sB + (warp_n * 32 + j * 16) * LDO + k0 * 16, LDO);
                wmma::mma_sync(acc[j], af, bf[j], acc[j]);
            }
        }
    }

    #pragma unroll
    for (int j = 0; j < 2; j++)
        wmma::store_matrix_sync(so + (warp_m * 16) * 132 + warp_n * 32 + j * 16,
                                acc[j], 132, wmma::mem_row_major);
    __syncthreads();

    // bias + MDN reorder: out[(e/20)][n][e%20]
    #pragma unroll
    for (int idx = t; idx < 32 * NOUT; idx += 256) {
        const int r = idx / NOUT;
        const int e = idx % NOUT;
        const float v = so[r * 132 + e] + b_out[e];
        out[(e / MIX) * (NP * MIX) + (row0 + r) * MIX + (e % MIX)] = v;
    }
}

// ---------------- launch ----------------
extern "C" void kernel_launch(void* const* d_in, const int* in_sizes, int n_in,
                              void* d_out, int out_size) {
    const float* xabs  = (const float*)d_in[0];
    const float* h0    = (const float*)d_in[1];
    const float* c0    = (const float*)d_in[2];
    const float* W_emb = (const float*)d_in[3];
    const float* b_emb = (const float*)d_in[4];
    const float* W_soc = (const float*)d_in[5];
    const float* b_soc = (const float*)d_in[6];
    const float* W_ih  = (const float*)d_in[7];
    const float* W_hh  = (const float*)d_in[8];
    const float* b_ih  = (const float*)d_in[9];
    const float* b_hh  = (const float*)d_in[10];
    const float* W_out = (const float*)d_in[11];
    const float* b_out = (const float*)d_in[12];
    float* out = (float*)d_out;

    cudaFuncSetAttribute(mma_P_kernel, cudaFuncAttributeMaxDynamicSharedMemorySize, SMEM_P_BYTES);
    cudaFuncSetAttribute(gates_lstm_kernel, cudaFuncAttributeMaxDynamicSharedMemorySize, SMEM_G_BYTES);
    cudaFuncSetAttribute(out_kernel, cudaFuncAttributeMaxDynamicSharedMemorySize, SMEM_O_BYTES);

    mma_P_kernel<<<dim3(8, 32), 256, SMEM_P_BYTES>>>(h0, W_soc);
    scatter_kernel<<<NP, 512>>>(xabs, h0, W_emb, b_emb, b_soc);
    gates_lstm_kernel<<<dim3(16, 8), 256, SMEM_G_BYTES>>>(W_ih, W_hh, b_ih, b_hh, c0);
    out_kernel<<<32, 256, SMEM_O_BYTES>>>(W_out, b_out, out);
}

// round 7
// speedup vs baseline: 4.7542x; 1.0440x over previous
#include <cuda_runtime.h>
#include <cuda_bf16.h>
#include <mma.h>
#include <math.h>
#include <stdint.h>

using namespace nvcuda;

typedef unsigned long long ull;

#define NP     1024
#define EMBD   64
#define HID    128
#define NCELL  64
#define PN     4096     // NCELL * EMBD
#define KX     256      // [emb(64) | pool(64) | h0(128)]
#define MIX    20
#define NOUT   120

// ---------------- device scratch (static, no allocations) ----------------
__device__ float g_P[NP * PN];        // 16 MB: P[m, c*64+e]
__device__ float g_X[NP * KX];        // 1 MB
__device__ float g_h[NP * HID];       // 0.5 MB

__device__ __forceinline__ float sigm(float x) { return 1.0f / (1.0f + expf(-x)); }

// split one float4 into hi/lo bf16x2 pairs and store to smem
__device__ __forceinline__ void split_store(__nv_bfloat16* d1, __nv_bfloat16* d2, float4 v) {
    __nv_bfloat162 h1a, h1b, h2a, h2b;
    h1a.x = __float2bfloat16(v.x); h2a.x = __float2bfloat16(v.x - __bfloat162float(h1a.x));
    h1a.y = __float2bfloat16(v.y); h2a.y = __float2bfloat16(v.y - __bfloat162float(h1a.y));
    h1b.x = __float2bfloat16(v.z); h2b.x = __float2bfloat16(v.z - __bfloat162float(h1b.x));
    h1b.y = __float2bfloat16(v.w); h2b.y = __float2bfloat16(v.w - __bfloat162float(h1b.y));
    *(__nv_bfloat162*)(d1)     = h1a;
    *(__nv_bfloat162*)(d1 + 2) = h1b;
    *(__nv_bfloat162*)(d2)     = h2a;
    *(__nv_bfloat162*)(d2 + 2) = h2b;
}

// ============ K1: WMMA bf16 P-GEMM with in-kernel fp32->bf16 split ============
// P = A1@B1^T + A2@B1^T + A1@B2^T, fp32 acc. CTA tile 128x128, K=128 resident.
#define LDP 136
#define TILEP (128 * LDP)
#define SMEM_P_BYTES (4 * TILEP * 2)

__global__ __launch_bounds__(256, 1) void mma_P_kernel(const float* __restrict__ h0,
                                                       const float* __restrict__ Wsoc) {
    extern __shared__ __align__(16) __nv_bfloat16 smemP[];
    __nv_bfloat16* sA1 = smemP;
    __nv_bfloat16* sA2 = smemP + TILEP;
    __nv_bfloat16* sB1 = smemP + 2 * TILEP;
    __nv_bfloat16* sB2 = smemP + 3 * TILEP;

    const int t   = threadIdx.x;
    const int wid = t >> 5;
    const int warp_m = wid & 1;      // 64-row half
    const int warp_n = wid >> 1;     // 32-col quarter
    const int row0 = blockIdx.x * 128;
    const int col0 = blockIdx.y * 128;

    #pragma unroll
    for (int i = t; i < 4096; i += 256) {
        const int row = i >> 5, k4 = i & 31;
        const float4 v = *(const float4*)&h0[(row0 + row) * HID + k4 * 4];
        split_store(sA1 + row * LDP + k4 * 4, sA2 + row * LDP + k4 * 4, v);
    }
    #pragma unroll
    for (int i = t; i < 4096; i += 256) {
        const int row = i >> 5, k4 = i & 31;
        const int ce = col0 + row;
        const int e = ce & 63, c = ce >> 6;
        const float4 v = *(const float4*)&Wsoc[e * (NCELL * HID) + c * HID + k4 * 4];
        split_store(sB1 + row * LDP + k4 * 4, sB2 + row * LDP + k4 * 4, v);
    }
    __syncthreads();

    wmma::fragment<wmma::accumulator, 16, 16, 16, float> acc[4][2];
    #pragma unroll
    for (int i = 0; i < 4; i++)
        #pragma unroll
        for (int j = 0; j < 2; j++)
            wmma::fill_fragment(acc[i][j], 0.0f);

    wmma::fragment<wmma::matrix_a, 16, 16, 16, __nv_bfloat16, wmma::row_major> af;
    wmma::fragment<wmma::matrix_b, 16, 16, 16, __nv_bfloat16, wmma::col_major> bf[2];

    #pragma unroll
    for (int term = 0; term < 3; term++) {
        const __nv_bfloat16* sA = (term == 1) ? sA2 : sA1;
        const __nv_bfloat16* sB = (term == 2) ? sB2 : sB1;
        #pragma unroll
        for (int k0 = 0; k0 < 8; k0++) {
            #pragma unroll
            for (int j = 0; j < 2; j++)
                wmma::load_matrix_sync(bf[j], sB + (warp_n * 32 + j * 16) * LDP + k0 * 16, LDP);
            #pragma unroll
            for (int i = 0; i < 4; i++) {
                wmma::load_matrix_sync(af, sA + (warp_m * 64 + i * 16) * LDP + k0 * 16, LDP);
                wmma::mma_sync(acc[i][0], af, bf[0], acc[i][0]);
                wmma::mma_sync(acc[i][1], af, bf[1], acc[i][1]);
            }
        }
    }

    #pragma unroll
    for (int i = 0; i < 4; i++)
        #pragma unroll
        for (int j = 0; j < 2; j++) {
            float* dst = g_P + (size_t)(row0 + warp_m * 64 + i * 16) * PN
                             + col0 + warp_n * 32 + j * 16;
            wmma::store_matrix_sync(dst, acc[i][j], PN, wmma::mem_row_major);
        }
}

// ============ K2: pair gather + X assembly (512 threads per pedestrian n) ============
__global__ __launch_bounds__(512) void scatter_kernel(const float* __restrict__ xabs,
                                                      const float* __restrict__ h0,
                                                      const float* __restrict__ W_emb,
                                                      const float* __restrict__ b_emb,
                                                      const float* __restrict__ b_soc) {
    __shared__ float sx[NP];
    __shared__ float sy[NP];
    __shared__ int   slist[NP];
    __shared__ int   wcnt[16];
    __shared__ float sred[8][64];

    const int n = blockIdx.x;
    const int t = threadIdx.x;
    const int w = t >> 5;
    const int lane = t & 31;

    for (int i = t; i < NP; i += 512) {
        const float2 v = ((const float2*)xabs)[i];
        sx[i] = v.x;
        sy[i] = v.y;
    }
    __syncthreads();

    const float wl = sx[n] - 0.2f;
    const float bl = sy[n] - 0.2f;

    int cells[2];
    unsigned masks[2];
    int cnt = 0;
    #pragma unroll
    for (int j = 0; j < 2; j++) {
        const int m = w * 64 + j * 32 + lane;
        const float dx = sx[m] - wl;
        const float dy = sy[m] - bl;
        int cell = -1;
        if (dx >= 0.0f && dx < 0.4f && dy >= 0.0f && dy < 0.4f && m != n) {
            const int cx = (int)floorf(__fmul_rn(__fdiv_rn(dx, 0.4f), 8.0f));
            const int cy = (int)floorf(__fmul_rn(__fdiv_rn(dy, 0.4f), 8.0f));
            if (cx >= 0 && cx < 8 && cy >= 0 && cy < 8) cell = cx + cy * 8;
        }
        cells[j] = (cell >= 0) ? (m * PN + cell * EMBD) : -1;
        masks[j] = __ballot_sync(0xFFFFFFFFu, cell >= 0);
        cnt += __popc(masks[j]);
    }
    if (lane == 0) wcnt[w] = cnt;

    if (t < 128) {
        g_X[n * KX + 128 + t] = h0[n * HID + t];
    } else if (t < 192) {
        const int e2 = t - 128;
        const float e = sx[n] * W_emb[2 * e2] + sy[n] * W_emb[2 * e2 + 1] + b_emb[e2];
        g_X[n * KX + e2] = fmaxf(e, 0.0f);
    }
    __syncthreads();

    int base = 0, tot = 0;
    #pragma unroll
    for (int ww = 0; ww < 16; ww++) {
        if (ww < w) base += wcnt[ww];
        tot += wcnt[ww];
    }
    #pragma unroll
    for (int j = 0; j < 2; j++) {
        if (cells[j] >= 0) {
            slist[base + __popc(masks[j] & ((1u << lane) - 1u))] = cells[j];
        }
        base += __popc(masks[j]);
    }
    __syncthreads();

    const int slot = t >> 6;
    const int e    = t & 63;
    float acc = 0.0f;
    int i = slot;
    for (; i + 16 <= tot; i += 16) {
        acc += g_P[(size_t)slist[i] + e];
        acc += g_P[(size_t)slist[i + 8] + e];
    }
    for (; i < tot; i += 8) acc += g_P[(size_t)slist[i] + e];
    sred[slot][e] = acc;
    __syncthreads();

    if (t < 64) {
        float s = b_soc[e];
        #pragma unroll
        for (int sl = 0; sl < 8; sl++) s += sred[sl][e];
        g_X[n * KX + 64 + e] = fmaxf(s, 0.0f);
    }
}

// ============ K3: WMMA gates GEMM fused with LSTM cell ============
#define LDG 264
#define TILEG (64 * LDG)
#define SMEM_G_BYTES (4 * TILEG * 2 + 64 * 68 * 4)

__global__ __launch_bounds__(256, 1) void gates_lstm_kernel(const float* __restrict__ W_ih,
                                                            const float* __restrict__ W_hh,
                                                            const float* __restrict__ b_ih,
                                                            const float* __restrict__ b_hh,
                                                            const float* __restrict__ c0) {
    extern __shared__ __align__(16) __nv_bfloat16 smemG[];
    __nv_bfloat16* sA1 = smemG;
    __nv_bfloat16* sA2 = smemG + TILEG;
    __nv_bfloat16* sB1 = smemG + 2 * TILEG;
    __nv_bfloat16* sB2 = smemG + 3 * TILEG;
    float* sg = (float*)(smemG + 4 * TILEG);   // [64][68]

    const int row0 = blockIdx.x * 64;
    const int d0   = blockIdx.y * 16;
    const int t   = threadIdx.x;
    const int wid = t >> 5;
    const int warp_m = wid & 3;
    const int warp_n = wid >> 2;

    #pragma unroll
    for (int i = t; i < 4096; i += 256) {
        const int row = i >> 6, k4 = i & 63;
        const float4 v = *(const float4*)&g_X[(row0 + row) * KX + k4 * 4];
        split_store(sA1 + row * LDG + k4 * 4, sA2 + row * LDG + k4 * 4, v);
    }
    #pragma unroll
    for (int i = t; i < 4096; i += 256) {
        const int cc = i >> 6, k4 = i & 63;
        const int wrow = (cc >> 4) * 128 + d0 + (cc & 15);
        const float4 v = (k4 < 32) ? *(const float4*)&W_ih[wrow * 128 + k4 * 4]
                                   : *(const float4*)&W_hh[wrow * 128 + (k4 - 32) * 4];
        split_store(sB1 + cc * LDG + k4 * 4, sB2 + cc * LDG + k4 * 4, v);
    }
    __syncthreads();

    wmma::fragment<wmma::accumulator, 16, 16, 16, float> acc[2];
    wmma::fill_fragment(acc[0], 0.0f);
    wmma::fill_fragment(acc[1], 0.0f);

    wmma::fragment<wmma::matrix_a, 16, 16, 16, __nv_bfloat16, wmma::row_major> af;
    wmma::fragment<wmma::matrix_b, 16, 16, 16, __nv_bfloat16, wmma::col_major> bf[2];

    #pragma unroll
    for (int term = 0; term < 3; term++) {
        const __nv_bfloat16* sA = (term == 1) ? sA2 : sA1;
        const __nv_bfloat16* sB = (term == 2) ? sB2 : sB1;
        #pragma unroll
        for (int k0 = 0; k0 < 16; k0++) {
            wmma::load_matrix_sync(af, sA + (warp_m * 16) * LDG + k0 * 16, LDG);
            #pragma unroll
            for (int j = 0; j < 2; j++) {
                wmma::load_matrix_sync(bf[j], sB + (warp_n * 32 + j * 16) * LDG + k0 * 16, LDG);
                wmma::mma_sync(acc[j], af, bf[j], acc[j]);
            }
        }
    }

    #pragma unroll
    for (int j = 0; j < 2; j++)
        wmma::store_matrix_sync(sg + (warp_m * 16) * 68 + warp_n * 32 + j * 16,
                                acc[j], 68, wmma::mem_row_major);
    __syncthreads();

    #pragma unroll
    for (int idx = t; idx < 1024; idx += 256) {
        const int rl = idx >> 4;
        const int dd = idx & 15;
        const int d = d0 + dd;
        const float ig = sg[rl * 68 + dd]      + b_ih[d]       + b_hh[d];
        const float fg = sg[rl * 68 + 16 + dd] + b_ih[128 + d] + b_hh[128 + d];
        const float gg = sg[rl * 68 + 32 + dd] + b_ih[256 + d] + b_hh[256 + d];
        const float og = sg[rl * 68 + 48 + dd] + b_ih[384 + d] + b_hh[384 + d];
        const int n = row0 + rl;
        const float c = sigm(fg) * c0[n * HID + d] + sigm(ig) * tanhf(gg);
        g_h[n * HID + d] = sigm(og) * tanhf(c);
    }
}

// ============ K4: WMMA output projection, retiled for occupancy ============
// CTA tile 16 rows x 64 cols, grid (64, 2) = 128 CTAs, 128 threads (4 warps, 1 frag each).
// Static smem (47.5 KB) -> 4 CTAs/SM.
#define LDO 136

__global__ __launch_bounds__(128) void out_kernel(const float* __restrict__ W_out,
                                                  const float* __restrict__ b_out,
                                                  float* __restrict__ out) {
    __shared__ __align__(16) __nv_bfloat16 sA1[16 * LDO];
    __shared__ __align__(16) __nv_bfloat16 sA2[16 * LDO];
    __shared__ __align__(16) __nv_bfloat16 sB1[64 * LDO];
    __shared__ __align__(16) __nv_bfloat16 sB2[64 * LDO];
    __shared__ float so[16 * 68];

    const int row0 = blockIdx.x * 16;
    const int col0 = blockIdx.y * 64;     // output-column base (0 or 64)
    const int t   = threadIdx.x;
    const int wid = t >> 5;               // 4 warps, warp_n = wid

    // load + split h tile: 16 rows x 32 float4
    #pragma unroll
    for (int i = t; i < 512; i += 128) {
        const int row = i >> 5, k4 = i & 31;
        const float4 v = *(const float4*)&g_h[(row0 + row) * HID + k4 * 4];
        split_store(sA1 + row * LDO + k4 * 4, sA2 + row * LDO + k4 * 4, v);
    }
    // load + split W_out half: 64 rows x 32 float4, zero-pad rows >= NOUT
    #pragma unroll
    for (int i = t; i < 2048; i += 128) {
        const int ee = i >> 5, k4 = i & 31;
        const int eg = col0 + ee;
        const float4 v = (eg < NOUT) ? *(const float4*)&W_out[eg * HID + k4 * 4]
                                     : make_float4(0.f, 0.f, 0.f, 0.f);
        split_store(sB1 + ee * LDO + k4 * 4, sB2 + ee * LDO + k4 * 4, v);
    }
    __syncthreads();

    wmma::fragment<wmma::accumulator, 16, 16, 16, float> acc;
    wmma::fill_fragment(acc, 0.0f);

    wmma::fragment<wmma::matrix_a, 16, 16, 16, __nv_bfloat16, wmma::row_major> af;
    wmma::fragment<wmma::matrix_b, 16, 16, 16, __nv_bfloat16, wmma::col_major> bf;

    #pragma unroll
    for (int term = 0; term < 3; term++) {
        const __nv_bfloat16* sA = (term == 1) ? sA2 : sA1;
        const __nv_bfloat16* sB = (term == 2) ? sB2 : sB1;
        #pragma unroll
        for (int k0 = 0; k0 < 8; k0++) {
            wmma::load_matrix_sync(af, sA + k0 * 16, LDO);
            wmma::load_matrix_sync(bf, sB + (wid * 16) * LDO + k0 * 16, LDO);
            wmma::mma_sync(acc, af, bf, acc);
        }
    }

    wmma::store_matrix_sync(so + wid * 16, acc, 68, wmma::mem_row_major);
    __syncthreads();

    // bias + MDN reorder: out[(e/20)][n][e%20]
    #pragma unroll
    for (int idx = t; idx < 16 * 64; idx += 128) {
        const int r  = idx >> 6;
        const int cc = idx & 63;
        const int e  = col0 + cc;
        if (e < NOUT) {
            const float v = so[r * 68 + cc] + b_out[e];
            out[(e / MIX) * (NP * MIX) + (row0 + r) * MIX + (e % MIX)] = v;
        }
    }
}

// ---------------- launch ----------------
extern "C" void kernel_launch(void* const* d_in, const int* in_sizes, int n_in,
                              void* d_out, int out_size) {
    const float* xabs  = (const float*)d_in[0];
    const float* h0    = (const float*)d_in[1];
    const float* c0    = (const float*)d_in[2];
    const float* W_emb = (const float*)d_in[3];
    const float* b_emb = (const float*)d_in[4];
    const float* W_soc = (const float*)d_in[5];
    const float* b_soc = (const float*)d_in[6];
    const float* W_ih  = (const float*)d_in[7];
    const float* W_hh  = (const float*)d_in[8];
    const float* b_ih  = (const float*)d_in[9];
    const float* b_hh  = (const float*)d_in[10];
    const float* W_out = (const float*)d_in[11];
    const float* b_out = (const float*)d_in[12];
    float* out = (float*)d_out;

    cudaFuncSetAttribute(mma_P_kernel, cudaFuncAttributeMaxDynamicSharedMemorySize, SMEM_P_BYTES);
    cudaFuncSetAttribute(gates_lstm_kernel, cudaFuncAttributeMaxDynamicSharedMemorySize, SMEM_G_BYTES);

    mma_P_kernel<<<dim3(8, 32), 256, SMEM_P_BYTES>>>(h0, W_soc);
    scatter_kernel<<<NP, 512>>>(xabs, h0, W_emb, b_emb, b_soc);
    gates_lstm_kernel<<<dim3(16, 8), 256, SMEM_G_BYTES>>>(W_ih, W_hh, b_ih, b_hh, c0);
    out_kernel<<<dim3(64, 2), 128>>>(W_out, b_out, out);
}